// round 6
// baseline (speedup 1.0000x reference)
#include <cuda_runtime.h>
#include <cuda_bf16.h>
#include <cstdint>
#include <cstddef>

#define B_SZ  16384
#define H     512
#define KD    1152      // 128 + 2*512
#define NTOT  2560      // 5 gates * 512
#define KC    16        // k per pipeline chunk
#define NCH   (KD/KC)   // 72
#define LDA   20        // padded smem row stride (floats)
#define LDB   20

// 160 MB scratch for pre-activations C[B, 5*H] (device global: no allocation calls)
__device__ float g_C[(size_t)B_SZ * NTOT];

__device__ __forceinline__ void cp16(void* dst_smem, const void* src) {
    uint32_t d = (uint32_t)__cvta_generic_to_shared(dst_smem);
    asm volatile("cp.async.ca.shared.global [%0], [%1], 16;\n" :: "r"(d), "l"(src));
}
__device__ __forceinline__ void cp_commit() { asm volatile("cp.async.commit_group;\n"); }
__device__ __forceinline__ void cp_wait0()  { asm volatile("cp.async.wait_group 0;\n"); }

__device__ __forceinline__ uint32_t f2tf(float f) {
    uint32_t u; asm("cvt.rna.tf32.f32 %0, %1;" : "=r"(u) : "f"(f)); return u;
}

// ---------------------------------------------------------------------------
// GEMM: C[m, n] = sum_k X[m,k] * W[n,k]
//   X[m,k]: k<128 -> label[m,k]; k<640 -> h0[m,k-128]; else h1[m,k-640]
//   W[n,k]: n<512 Wi; <1024 Wo; <1536 Wu; else f-gate kk=(n-1536)/512:
//           k<128 -> Wfl[h,k]; else Wfs[kk, j=(k-128)/512, h, (k-128)%512]
// CTA tile 128x128, 8 warps (4m x 2n), warp tile 32x64, mma m16n8k8 tf32.
// ---------------------------------------------------------------------------
__global__ void __launch_bounds__(256) gemm_kernel(
    const float* __restrict__ label, const float* __restrict__ chh,
    const float* __restrict__ Wi, const float* __restrict__ Wo,
    const float* __restrict__ Wu, const float* __restrict__ Wfl,
    const float* __restrict__ Wfs)
{
    __shared__ float As[2][128 * LDA];
    __shared__ float Bs[2][128 * LDB];

    const int tid  = threadIdx.x;
    const int warp = tid >> 5, lane = tid & 31;
    const int wm = (warp >> 1) * 32;     // warp m offset in tile
    const int wn = (warp & 1) * 64;      // warp n offset in tile
    const int m0 = blockIdx.y * 128;     // global m base
    const int nt = blockIdx.x;           // n tile 0..19
    const int gate = nt >> 2;            // 0..4
    const int ng = (nt & 3) * 128;       // n offset within gate

    float acc[2][8][4];
    #pragma unroll
    for (int a = 0; a < 2; a++)
        #pragma unroll
        for (int b = 0; b < 8; b++)
            #pragma unroll
            for (int c = 0; c < 4; c++) acc[a][b][c] = 0.f;

    auto loadA = [&](int buf, int c) {
        const int k0 = c * KC;
        const float* base; int stride, col0;
        if (k0 < 128)      { base = label;                    stride = 128; col0 = k0;       }
        else if (k0 < 640) { base = chh;                      stride = 512; col0 = k0 - 128; }
        else               { base = chh + (size_t)B_SZ * 512; stride = 512; col0 = k0 - 640; }
        #pragma unroll
        for (int i = 0; i < 2; i++) {
            int ci = tid + i * 256;               // 512 chunks of 16B
            int r = ci >> 2, cc = (ci & 3) * 4;   // row, col4
            cp16(&As[buf][r * LDA + cc], base + (size_t)(m0 + r) * stride + col0 + cc);
        }
    };
    auto loadB = [&](int buf, int c) {
        const int k0 = c * KC;
        const float* base; int stride;
        if (gate < 3) {
            const float* W = (gate == 0) ? Wi : ((gate == 1) ? Wo : Wu);
            base = W + (size_t)ng * KD + k0; stride = KD;
        } else {
            const int kk = gate - 3;
            if (k0 < 128) { base = Wfl + (size_t)ng * 128 + k0; stride = 128; }
            else {
                int j = (k0 - 128) >> 9;
                int kcol = k0 - 128 - (j << 9);
                base = Wfs + ((size_t)(kk * 2 + j) * 512 + ng) * 512 + kcol;
                stride = 512;
            }
        }
        #pragma unroll
        for (int i = 0; i < 2; i++) {
            int ci = tid + i * 256;
            int r = ci >> 2, cc = (ci & 3) * 4;
            cp16(&Bs[buf][r * LDB + cc], base + (size_t)r * stride + cc);
        }
    };

    loadA(0, 0); loadB(0, 0); cp_commit();

    for (int c = 0; c < NCH; c++) {
        cp_wait0();
        __syncthreads();
        if (c + 1 < NCH) { loadA((c + 1) & 1, c + 1); loadB((c + 1) & 1, c + 1); cp_commit(); }
        const int buf = c & 1;
        #pragma unroll
        for (int ks = 0; ks < 2; ks++) {
            const int kb = ks * 8;
            const int cA = kb + (lane & 3);
            uint32_t aR[2][4];
            #pragma unroll
            for (int mf = 0; mf < 2; mf++) {
                int r = wm + mf * 16 + (lane >> 2);
                aR[mf][0] = f2tf(As[buf][r * LDA + cA]);
                aR[mf][1] = f2tf(As[buf][(r + 8) * LDA + cA]);
                aR[mf][2] = f2tf(As[buf][r * LDA + cA + 4]);
                aR[mf][3] = f2tf(As[buf][(r + 8) * LDA + cA + 4]);
            }
            #pragma unroll
            for (int nf = 0; nf < 8; nf++) {
                int n = wn + nf * 8 + (lane >> 2);
                uint32_t b0 = f2tf(Bs[buf][n * LDB + cA]);
                uint32_t b1 = f2tf(Bs[buf][n * LDB + cA + 4]);
                #pragma unroll
                for (int mf = 0; mf < 2; mf++) {
                    asm volatile(
                        "mma.sync.aligned.m16n8k8.row.col.f32.tf32.tf32.f32 "
                        "{%0,%1,%2,%3}, {%4,%5,%6,%7}, {%8,%9}, {%0,%1,%2,%3};\n"
                        : "+f"(acc[mf][nf][0]), "+f"(acc[mf][nf][1]),
                          "+f"(acc[mf][nf][2]), "+f"(acc[mf][nf][3])
                        : "r"(aR[mf][0]), "r"(aR[mf][1]), "r"(aR[mf][2]), "r"(aR[mf][3]),
                          "r"(b0), "r"(b1));
                }
            }
        }
        __syncthreads();
    }

    // store C tile
    const size_t nbase = (size_t)nt * 128;
    #pragma unroll
    for (int mf = 0; mf < 2; mf++) {
        const size_t r = (size_t)(m0 + wm + mf * 16 + (lane >> 2));
        #pragma unroll
        for (int nf = 0; nf < 8; nf++) {
            size_t n = nbase + wn + nf * 8 + (lane & 3) * 2;
            *(float2*)&g_C[r * NTOT + n]       = make_float2(acc[mf][nf][0], acc[mf][nf][1]);
            *(float2*)&g_C[(r + 8) * NTOT + n] = make_float2(acc[mf][nf][2], acc[mf][nf][3]);
        }
    }
}

// ---------------------------------------------------------------------------
// Elementwise epilogue: gates -> (next_cell, out)
// ---------------------------------------------------------------------------
__global__ void __launch_bounds__(256) epilogue_kernel(
    const float* __restrict__ chc,
    const float* __restrict__ bi, const float* __restrict__ bo,
    const float* __restrict__ bu, const float* __restrict__ fb,
    float* __restrict__ out)
{
    const int idx = blockIdx.x * 256 + threadIdx.x;   // b*512 + h
    const int h = idx & (H - 1);
    const size_t row = (size_t)(idx >> 9) * NTOT;
    float pi  = g_C[row + h];
    float po  = g_C[row + 512 + h];
    float pu  = g_C[row + 1024 + h];
    float pf0 = g_C[row + 1536 + h];
    float pf1 = g_C[row + 2048 + h];
    float c0 = chc[idx];
    float c1 = chc[(size_t)B_SZ * H + idx];
    float ig = 1.f / (1.f + __expf(-(pi + bi[h])));
    float og = 1.f / (1.f + __expf(-(po + bo[h])));
    float uu = tanhf(pu + bu[h]);
    float f0 = 1.f / (1.f + __expf(-pf0));
    float f1 = 1.f / (1.f + __expf(-pf1));
    float nc = ig * uu + f0 * c0 + f1 * c1 + fb[h] * (c0 + c1);
    out[idx] = nc;
    out[(size_t)B_SZ * H + idx] = tanhf(og * nc);
}

extern "C" void kernel_launch(void* const* d_in, const int* in_sizes, int n_in,
                              void* d_out, int out_size) {
    const float* label = (const float*)d_in[0];
    const float* chh   = (const float*)d_in[1];
    const float* chc   = (const float*)d_in[2];
    const float* Wi    = (const float*)d_in[3];
    const float* bi    = (const float*)d_in[4];
    const float* Wo    = (const float*)d_in[5];
    const float* bo    = (const float*)d_in[6];
    const float* Wu    = (const float*)d_in[7];
    const float* bu    = (const float*)d_in[8];
    const float* Wfl   = (const float*)d_in[9];
    const float* Wfs   = (const float*)d_in[10];
    const float* fb    = (const float*)d_in[11];
    float* out = (float*)d_out;

    dim3 grid(20, 128);                  // n-tiles fastest: X m-tile reused in L2
    gemm_kernel<<<grid, 256>>>(label, chh, Wi, Wo, Wu, Wfl, Wfs);
    epilogue_kernel<<<(B_SZ * H) / 256, 256>>>(chc, bi, bo, bu, fb, out);
}

// round 10
// speedup vs baseline: 1.5365x; 1.5365x over previous
#include <cuda_runtime.h>
#include <cstdint>
#include <cstddef>

#define BSZ   16384
#define H     512
#define KD    1152            // 128 + 2*512
#define NTOT  2560            // 5 gates * 512
#define KC    16
#define NCH   (KD / KC)       // 72
#define NTILES 20             // 2560 / 128
#define MTILES 128            // 16384 / 128
// one packed chunk block = 8 subtiles * 2 ks * 32 lanes * 16B = 8 KB = 512 float4

// --------- device-global scratch (no allocation calls anywhere) ----------
static __device__ float g_Xp[(size_t)BSZ * KD];          // 75.5 MB, fragment-ordered
static __device__ float g_Wp[(size_t)NTOT * KD];         // 11.8 MB, fragment-ordered
static __device__ float g_C[(size_t)BSZ * NTOT];         // 160 MB pre-activations

// ------------------------------ helpers ---------------------------------
__device__ __forceinline__ float tfr(float f) {          // round-to-nearest tf32
    uint32_t u; asm("cvt.rna.tf32.f32 %0, %1;" : "=r"(u) : "f"(f));
    return __uint_as_float(u);
}
__device__ __forceinline__ void cp16(uint32_t dst, const void* src) {
    asm volatile("cp.async.ca.shared.global [%0], [%1], 16;\n" :: "r"(dst), "l"(src));
}
#define MMA(acc, a, b0, b1)                                                    \
    asm volatile("mma.sync.aligned.m16n8k8.row.col.f32.tf32.tf32.f32 "         \
                 "{%0,%1,%2,%3}, {%4,%5,%6,%7}, {%8,%9}, {%0,%1,%2,%3};\n"     \
                 : "+f"(acc[0]), "+f"(acc[1]), "+f"(acc[2]), "+f"(acc[3])      \
                 : "r"(a.x), "r"(a.y), "r"(a.z), "r"(a.w), "r"(b0), "r"(b1))

// ------------------------------ pack X ----------------------------------
// g_Xp float4 index: (((mt128*72 + chunk)*8 + mt16)*2 + ks)*32 + lane
// fragment: e0=X(r,c) e1=X(r+8,c) e2=X(r,c+4) e3=X(r+8,c+4)
//   r = mt128*128 + mt16*16 + (lane>>2),  c = chunk*16 + ks*8 + (lane&3)
__global__ void __launch_bounds__(256) pack_x(const float* __restrict__ label,
                                              const float* __restrict__ chh) {
    const size_t i4 = (size_t)blockIdx.x * 256 + threadIdx.x;
    const int lane = (int)(i4 & 31);
    const int ks   = (int)((i4 >> 5) & 1);
    const int mt16 = (int)((i4 >> 6) & 7);
    const size_t blk = i4 >> 9;
    const int chunk = (int)(blk % NCH);
    const int mt128 = (int)(blk / NCH);

    const int r = mt128 * 128 + mt16 * 16 + (lane >> 2);
    const int c = chunk * 16 + ks * 8 + (lane & 3);

    const float* base; int stride, cc;
    if (c < 128)      { base = label;                    stride = 128; cc = c;       }
    else if (c < 640) { base = chh;                      stride = 512; cc = c - 128; }
    else              { base = chh + (size_t)BSZ * 512;  stride = 512; cc = c - 640; }

    float4 o;
    o.x = tfr(base[(size_t)r       * stride + cc]);
    o.y = tfr(base[(size_t)(r + 8) * stride + cc]);
    o.z = tfr(base[(size_t)r       * stride + cc + 4]);
    o.w = tfr(base[(size_t)(r + 8) * stride + cc + 4]);
    ((float4*)g_Xp)[i4] = o;
}

// ------------------------------ pack W ----------------------------------
// W(n,k): gate = n>>9, h = n&511
//   gate 0..2 -> Wi/Wo/Wu[h*1152 + k]
//   gate 3..4 -> kk=gate-3: k<128 -> Wfl[h*128+k]
//                else j=(k-128)>>9, kc=(k-128)&511 -> Wfs[((kk*2+j)*512+h)*512+kc]
__device__ __forceinline__ float wval(int n, int k,
    const float* Wi, const float* Wo, const float* Wu,
    const float* Wfl, const float* Wfs) {
    const int gate = n >> 9, h = n & 511;
    if (gate == 0) return Wi[(size_t)h * KD + k];
    if (gate == 1) return Wo[(size_t)h * KD + k];
    if (gate == 2) return Wu[(size_t)h * KD + k];
    const int kk = gate - 3;
    if (k < 128) return Wfl[(size_t)h * 128 + k];
    const int j = (k - 128) >> 9, kc = (k - 128) & 511;
    return Wfs[(((size_t)(kk * 2 + j)) * 512 + h) * 512 + kc];
}

// g_Wp float4 index: (((nt128*72 + chunk)*8 + pair)*2 + ks)*32 + lane
// fragment pair: e0=W(n0,k) e1=W(n0,k+4) e2=W(n1,k) e3=W(n1,k+4)
//   n0 = nt128*128 + pair*16 + (lane>>2), n1 = n0+8, k = chunk*16 + ks*8 + (lane&3)
__global__ void __launch_bounds__(256) pack_w(
    const float* __restrict__ Wi, const float* __restrict__ Wo,
    const float* __restrict__ Wu, const float* __restrict__ Wfl,
    const float* __restrict__ Wfs) {
    const size_t i4 = (size_t)blockIdx.x * 256 + threadIdx.x;
    const int lane = (int)(i4 & 31);
    const int ks   = (int)((i4 >> 5) & 1);
    const int pair = (int)((i4 >> 6) & 7);
    const size_t blk = i4 >> 9;
    const int chunk = (int)(blk % NCH);
    const int nt128 = (int)(blk / NCH);

    const int n0 = nt128 * 128 + pair * 16 + (lane >> 2);
    const int n1 = n0 + 8;
    const int k  = chunk * 16 + ks * 8 + (lane & 3);

    float4 o;
    o.x = tfr(wval(n0, k,     Wi, Wo, Wu, Wfl, Wfs));
    o.y = tfr(wval(n0, k + 4, Wi, Wo, Wu, Wfl, Wfs));
    o.z = tfr(wval(n1, k,     Wi, Wo, Wu, Wfl, Wfs));
    o.w = tfr(wval(n1, k + 4, Wi, Wo, Wu, Wfl, Wfs));
    ((float4*)g_Wp)[i4] = o;
}

// ------------------------------- GEMM -----------------------------------
// CTA tile 128x128, 8 warps (4m x 2n), warp tile 32x64.
// smem per stage: A block 8KB (512 f4) + B block 8KB -> 16KB; 2 stages = 32KB.
__global__ void __launch_bounds__(256, 2) gemm_kernel() {
    __shared__ uint4 sm[2][1024];

    const int tid = threadIdx.x, warp = tid >> 5, lane = tid & 31;
    const int nt = blockIdx.x;            // 0..19  (fast dim: weights L2-hot)
    const int mt = blockIdx.y;            // 0..127
    const int wm2 = (warp >> 1) * 2;      // mtile16 base (0,2,4,6)
    const int wn4 = (warp & 1) * 4;       // B pair base (0 or 4)

    const float4* gA = (const float4*)g_Xp + (size_t)mt * NCH * 512;
    const float4* gB = (const float4*)g_Wp + (size_t)nt * NCH * 512;
    const uint32_t sb = (uint32_t)__cvta_generic_to_shared(sm);

    float acc[2][8][4];
    #pragma unroll
    for (int a = 0; a < 2; a++)
        #pragma unroll
        for (int b = 0; b < 8; b++)
            #pragma unroll
            for (int c = 0; c < 4; c++) acc[a][b][c] = 0.f;

    auto load = [&](int s, int c) {
        const float4* a = gA + (size_t)c * 512;
        const float4* b = gB + (size_t)c * 512;
        const uint32_t d = sb + s * 16384 + tid * 16;
        cp16(d,                a + tid);
        cp16(d + 4096,         a + tid + 256);
        cp16(d + 8192,         b + tid);
        cp16(d + 12288,        b + tid + 256);
    };

    load(0, 0);
    asm volatile("cp.async.commit_group;");

    #pragma unroll 1
    for (int c = 0; c < NCH; c++) {
        if (c + 1 < NCH) {
            load((c + 1) & 1, c + 1);
            asm volatile("cp.async.commit_group;");
            asm volatile("cp.async.wait_group 1;");
        } else {
            asm volatile("cp.async.wait_group 0;");
        }
        __syncthreads();

        const uint4* A4 = &sm[c & 1][0];
        const uint4* B4 = &sm[c & 1][512];
        #pragma unroll
        for (int ks = 0; ks < 2; ks++) {
            uint4 a0 = A4[((wm2 + 0) * 2 + ks) * 32 + lane];
            uint4 a1 = A4[((wm2 + 1) * 2 + ks) * 32 + lane];
            #pragma unroll
            for (int q = 0; q < 4; q++) {
                uint4 b = B4[((wn4 + q) * 2 + ks) * 32 + lane];
                MMA(acc[0][2 * q],     a0, b.x, b.y);
                MMA(acc[0][2 * q + 1], a0, b.z, b.w);
                MMA(acc[1][2 * q],     a1, b.x, b.y);
                MMA(acc[1][2 * q + 1], a1, b.z, b.w);
            }
        }
        __syncthreads();
    }

    // store C tile (fragment c-regs: c0,c1 @ (r, 2c), c2,c3 @ (r+8, 2c))
    const size_t nbase = (size_t)nt * 128;
    const int m0 = mt * 128;
    #pragma unroll
    for (int mf = 0; mf < 2; mf++) {
        const size_t r = (size_t)(m0 + (warp >> 1) * 32 + mf * 16 + (lane >> 2));
        #pragma unroll
        for (int nf = 0; nf < 8; nf++) {
            size_t n = nbase + (warp & 1) * 64 + nf * 8 + (lane & 3) * 2;
            *(float2*)&g_C[r * NTOT + n]       = make_float2(acc[mf][nf][0], acc[mf][nf][1]);
            *(float2*)&g_C[(r + 8) * NTOT + n] = make_float2(acc[mf][nf][2], acc[mf][nf][3]);
        }
    }
}

// ----------------------------- epilogue ---------------------------------
__global__ void __launch_bounds__(256) epilogue_kernel(
    const float* __restrict__ chc,
    const float* __restrict__ bi, const float* __restrict__ bo,
    const float* __restrict__ bu, const float* __restrict__ fb,
    float* __restrict__ out) {
    const size_t i4 = (size_t)blockIdx.x * 256 + threadIdx.x;  // B*H/4 float4s
    const int h = (int)(i4 & 127) * 4;
    const size_t b = i4 >> 7;
    const float* Crow = g_C + b * NTOT;
    const size_t OUT2 = (size_t)BSZ * H;

    float4 pi  = *(const float4*)(Crow + h);
    float4 po  = *(const float4*)(Crow + 512 + h);
    float4 pu  = *(const float4*)(Crow + 1024 + h);
    float4 pf0 = *(const float4*)(Crow + 1536 + h);
    float4 pf1 = *(const float4*)(Crow + 2048 + h);
    float4 c0  = *(const float4*)(chc + b * H + h);
    float4 c1  = *(const float4*)(chc + OUT2 + b * H + h);
    float4 vbi = *(const float4*)(bi + h);
    float4 vbo = *(const float4*)(bo + h);
    float4 vbu = *(const float4*)(bu + h);
    float4 vfb = *(const float4*)(fb + h);

    float4 nc, to;
    #define LANE(f)                                                             \
    {                                                                           \
        float ig = 1.f / (1.f + __expf(-(pi.f + vbi.f)));                       \
        float og = 1.f / (1.f + __expf(-(po.f + vbo.f)));                       \
        float uu = tanhf(pu.f + vbu.f);                                         \
        float f0 = 1.f / (1.f + __expf(-pf0.f));                                \
        float f1 = 1.f / (1.f + __expf(-pf1.f));                                \
        nc.f = ig * uu + f0 * c0.f + f1 * c1.f + vfb.f * (c0.f + c1.f);         \
        to.f = tanhf(og * nc.f);                                                \
    }
    LANE(x) LANE(y) LANE(z) LANE(w)
    #undef LANE

    *(float4*)(out + b * H + h)        = nc;
    *(float4*)(out + OUT2 + b * H + h) = to;
}

// ------------------------------- launch ---------------------------------
extern "C" void kernel_launch(void* const* d_in, const int* in_sizes, int n_in,
                              void* d_out, int out_size) {
    const float* label = (const float*)d_in[0];
    const float* chh   = (const float*)d_in[1];
    const float* chc   = (const float*)d_in[2];
    const float* Wi    = (const float*)d_in[3];
    const float* bi    = (const float*)d_in[4];
    const float* Wo    = (const float*)d_in[5];
    const float* bo    = (const float*)d_in[6];
    const float* Wu    = (const float*)d_in[7];
    const float* bu    = (const float*)d_in[8];
    const float* Wfl   = (const float*)d_in[9];
    const float* Wfs   = (const float*)d_in[10];
    const float* fb    = (const float*)d_in[11];
    float* out = (float*)d_out;

    pack_x<<<(BSZ / 4) * (KD / 4) / 64, 256>>>(label, chh);          // 18432 blocks
    pack_w<<<(NTOT / 4) * (KD / 4) / 64, 256>>>(Wi, Wo, Wu, Wfl, Wfs); // 2880*... = 11520 blocks
    gemm_kernel<<<dim3(NTILES, MTILES), 256>>>();
    epilogue_kernel<<<(BSZ * H / 4) / 256, 256>>>(chc, bi, bo, bu, fb, out);
}